// round 1
// baseline (speedup 1.0000x reference)
#include <cuda_runtime.h>
#include <cstdint>

// Rotation42d: per-sample rotation of (256, 3, 224, 224) fp32 by label in {0,1,2,3}.
//   r0  : out[h][w] = in[h][w]
//   r90 : out[h][w] = in[w][h]            (swapaxes(-2,-1))
//   r180: out[h][w] = in[H-1-h][w]        (flip(-2))
//   r270: out[h][w] = in[W-1-w][h]        (flip(swapaxes(-2,-1), -1))
// 224 = 7 * 32 exactly -> full 32x32 tiles, no bounds checks.

#define HW 224
#define TILES 7  // 224/32

__global__ __launch_bounds__(256) void rot_kernel(
    const float* __restrict__ x,
    const int*   __restrict__ label,
    float*       __restrict__ out)
{
    const int img = blockIdx.z;          // 0..767  (b*3 + c)
    const int b   = img / 3;
    const int lab = label[b] & 3;

    const int bx = blockIdx.x;           // tile col index of OUTPUT
    const int by = blockIdx.y;           // tile row index of OUTPUT
    const int tx = threadIdx.x;          // 0..31
    const int ty = threadIdx.y;          // 0..7

    const float* __restrict__ in = x   + (size_t)img * (HW * HW);
    float* __restrict__       o  = out + (size_t)img * (HW * HW);

    __shared__ float tile[32][33];       // +1 pad: conflict-free transposed reads

    if (lab == 0) {
        // identity: straight coalesced copy
        #pragma unroll
        for (int k = 0; k < 4; k++) {
            const int i = ty + k * 8;
            const int h = by * 32 + i;
            const int w = bx * 32 + tx;
            o[h * HW + w] = in[h * HW + w];
        }
    } else if (lab == 2) {
        // flip rows: both sides row-contiguous -> coalesced
        #pragma unroll
        for (int k = 0; k < 4; k++) {
            const int i = ty + k * 8;
            const int h = by * 32 + i;
            const int w = bx * 32 + tx;
            o[h * HW + w] = in[(HW - 1 - h) * HW + w];
        }
    } else if (lab == 1) {
        // transpose: out[by*32+i][bx*32+j] = in[bx*32+j][by*32+i]
        // load input tile rows [bx*32, bx*32+32), cols [by*32, by*32+32) coalesced
        #pragma unroll
        for (int k = 0; k < 4; k++) {
            const int i = ty + k * 8;
            tile[i][tx] = in[(bx * 32 + i) * HW + (by * 32 + tx)];
        }
        __syncthreads();
        #pragma unroll
        for (int k = 0; k < 4; k++) {
            const int i = ty + k * 8;
            o[(by * 32 + i) * HW + (bx * 32 + tx)] = tile[tx][i];
        }
    } else {
        // r270: out[h][w] = in[HW-1-w][h]
        // with h = by*32+i, w = bx*32+j:  in[HW-1-bx*32-j][by*32+i]
        // load tile[j][col] = in[HW-1-bx*32-j][by*32+col]  (coalesced in col)
        #pragma unroll
        for (int k = 0; k < 4; k++) {
            const int j = ty + k * 8;
            tile[j][tx] = in[(HW - 1 - (bx * 32 + j)) * HW + (by * 32 + tx)];
        }
        __syncthreads();
        #pragma unroll
        for (int k = 0; k < 4; k++) {
            const int i = ty + k * 8;
            o[(by * 32 + i) * HW + (bx * 32 + tx)] = tile[tx][i];
        }
    }
}

__global__ void label_tail_kernel(const int* __restrict__ label,
                                  float* __restrict__ out_tail, int n)
{
    const int i = blockIdx.x * blockDim.x + threadIdx.x;
    if (i < n) out_tail[i] = (float)label[i];
}

extern "C" void kernel_launch(void* const* d_in, const int* in_sizes, int n_in,
                              void* d_out, int out_size)
{
    const float* x     = (const float*)d_in[0];
    const int*   label = (const int*)d_in[1];
    float*       out   = (float*)d_out;

    const int n_label   = (n_in > 1) ? in_sizes[1] : 256;
    const long img_elems = 256L * 3L * HW * HW;  // 38,535,168

    dim3 grid(TILES, TILES, 256 * 3);
    dim3 block(32, 8);
    rot_kernel<<<grid, block>>>(x, label, out);

    // If the harness output includes the second tuple element (label),
    // append it converted to the output dtype.
    if ((long)out_size > img_elems) {
        const int tail = (int)((long)out_size - img_elems);
        const int nl = tail < n_label ? tail : n_label;
        label_tail_kernel<<<(nl + 127) / 128, 128>>>(label, out + img_elems, nl);
    }
}

// round 2
// speedup vs baseline: 1.0340x; 1.0340x over previous
#include <cuda_runtime.h>
#include <cstdint>

// Rotation42d: per-sample rotation of (256, 3, 224, 224) fp32 by label in {0,1,2,3}.
//   r0  : out[h][w] = in[h][w]
//   r90 : out[h][w] = in[w][h]
//   r180: out[h][w] = in[H-1-h][w]
//   r270: out[h][w] = in[W-1-w][h]
// 224 = 7*32 -> full 32x32 tiles, no bounds checks.
// All global traffic is 128-bit (float4). Transpose goes through a padded
// shared tile with conflict-free scalar STS/LDS.

#define HW 224
#define TILES 7  // 224/32

__global__ __launch_bounds__(256) void rot_kernel(
    const float4* __restrict__ x4,
    const int*    __restrict__ label,
    float4*       __restrict__ out4)
{
    const int img = blockIdx.z;          // 0..767  (b*3 + c)
    const int b   = img / 3;
    const int lab = label[b] & 3;

    const int bx = blockIdx.x;           // output tile col
    const int by = blockIdx.y;           // output tile row
    const int tx = threadIdx.x;          // 0..7   (float4 group within tile)
    const int ty = threadIdx.y;          // 0..31  (row within tile)

    // float4 view: each image row is HW/4 = 56 float4
    const int ROW4 = HW / 4;             // 56
    const float4* __restrict__ in = x4   + (size_t)img * (HW * ROW4);
    float4* __restrict__       o  = out4 + (size_t)img * (HW * ROW4);

    __shared__ float tile[32][33];       // 33-float pitch: conflict-free

    if (lab == 0) {
        // identity
        const int h = by * 32 + ty;
        const int g = bx * 8 + tx;       // float4 col group
        o[h * ROW4 + g] = in[h * ROW4 + g];
    } else if (lab == 2) {
        // flip rows
        const int h = by * 32 + ty;
        const int g = bx * 8 + tx;
        o[h * ROW4 + g] = in[(HW - 1 - h) * ROW4 + g];
    } else {
        // r90 / r270: both end in a transposed gather from the tile.
        // r90 : value(i, 4g+k) = in[bx*32 + 4g+k][by*32 + i]
        //       -> load tile[r][c] = in[bx*32 + r][by*32 + c]
        // r270: value(i, 4g+k) = in[HW-1 - (bx*32 + 4g+k)][by*32 + i]
        //       -> load tile[r][c] = in[HW-1 - (bx*32 + r)][by*32 + c]
        const int r = ty;                // input row within tile (0..31)
        const int src_row = (lab == 1) ? (bx * 32 + r)
                                       : (HW - 1 - (bx * 32 + r));
        // coalesced float4 load of 32 floats of that row (cols by*32 .. +32)
        const float4 v = in[src_row * ROW4 + (by * 8 + tx)];
        tile[r][4 * tx + 0] = v.x;
        tile[r][4 * tx + 1] = v.y;
        tile[r][4 * tx + 2] = v.z;
        tile[r][4 * tx + 3] = v.w;
        __syncthreads();

        // gather transposed: out[(by*32+i)][bx*32 + 4g + k] = tile[4g+k][i]
        const int i = ty;
        const int g = tx;
        float4 w;
        w.x = tile[4 * g + 0][i];
        w.y = tile[4 * g + 1][i];
        w.z = tile[4 * g + 2][i];
        w.w = tile[4 * g + 3][i];
        o[(by * 32 + i) * ROW4 + (bx * 8 + g)] = w;
    }
}

__global__ void label_tail_kernel(const int* __restrict__ label,
                                  float* __restrict__ out_tail, int n)
{
    const int i = blockIdx.x * blockDim.x + threadIdx.x;
    if (i < n) out_tail[i] = (float)label[i];
}

extern "C" void kernel_launch(void* const* d_in, const int* in_sizes, int n_in,
                              void* d_out, int out_size)
{
    const float4* x     = (const float4*)d_in[0];
    const int*    label = (const int*)d_in[1];
    float4*       out   = (float4*)d_out;

    const int n_label    = (n_in > 1) ? in_sizes[1] : 256;
    const long img_elems = 256L * 3L * HW * HW;  // 38,535,168

    dim3 grid(TILES, TILES, 256 * 3);
    dim3 block(8, 32);
    rot_kernel<<<grid, block>>>(x, label, out);

    if ((long)out_size > img_elems) {
        const int tail = (int)((long)out_size - img_elems);
        const int nl = tail < n_label ? tail : n_label;
        label_tail_kernel<<<(nl + 127) / 128, 128>>>(label,
                                                     (float*)d_out + img_elems, nl);
    }
}